// round 4
// baseline (speedup 1.0000x reference)
#include <cuda_runtime.h>
#include <cuda_bf16.h>
#include <math.h>

// Problem constants
#define BATCH 2
#define NPTS  4096
#define NG    (BATCH*NPTS)     // 8192 nodes total
#define DIM   128
#define MDIM  16
#define KNN_K 32
#define EH    530              // edge hidden dim (2*265)
#define EHP   544              // padded to 17*32
#define NODE_IN 144            // DIM + MDIM
#define NODE_H  256
#define NPB   8                // nodes per edge-kernel block

// -------------------- scratch (static device globals; no allocation) ----------
__device__ float d_A [NG * EHP];      // feats @ We1[0:128] + be1   (cols 530..543 stay 0)
__device__ float d_Bf[NG * EHP];      // feats @ We1[128:256]       (cols 530..543 stay 0)
__device__ int   d_idx[NG * KNN_K];
__device__ float d_mi [NG * MDIM];
__device__ float d_nodein[NG * NODE_IN];
__device__ float d_h  [NG * NODE_H];
__device__ float d_We2p[EHP * 16];    // zero-padded We2 (row k -> 16 cols)
__device__ float d_W1fp[9 * EHP];     // zero-padded fourier rows of We1

__device__ __forceinline__ float siluf(float x) {
    return x / (1.0f + __expf(-x));
}

// ---------------- packed f32x2 helpers (Blackwell FFMA2 path) ------------------
__device__ __forceinline__ unsigned long long pk2(float lo, float hi) {
    unsigned long long r; asm("mov.b64 %0, {%1,%2};" : "=l"(r) : "f"(lo), "f"(hi)); return r;
}
__device__ __forceinline__ void upk2(unsigned long long v, float &lo, float &hi) {
    asm("mov.b64 {%0,%1}, %2;" : "=f"(lo), "=f"(hi) : "l"(v));
}
__device__ __forceinline__ unsigned long long fma2(unsigned long long a,
                                                   unsigned long long b,
                                                   unsigned long long c) {
    unsigned long long d;
    asm("fma.rn.f32x2 %0, %1, %2, %3;" : "=l"(d) : "l"(a), "l"(b), "l"(c));
    return d;
}
__device__ __forceinline__ unsigned long long add2(unsigned long long a,
                                                   unsigned long long b) {
    unsigned long long d;
    asm("add.rn.f32x2 %0, %1, %2;" : "=l"(d) : "l"(a), "l"(b));
    return d;
}

// ---------------------- pad / transpose small weights --------------------------
__global__ void pad_weights_kernel(const float* __restrict__ We1,
                                   const float* __restrict__ We2)
{
    int i = blockIdx.x * blockDim.x + threadIdx.x;
    if (i < EHP * 16) {
        int k = i >> 4, t = i & 15;
        d_We2p[i] = (k < EH) ? We2[k * 16 + t] : 0.f;
    }
    if (i < 9 * EHP) {
        int t = i / EHP, k = i - t * EHP;
        d_W1fp[i] = (k < EH) ? We1[(256 + t) * EH + k] : 0.f;
    }
}

// ------------------------------ KNN -------------------------------------------
// Cached-candidate selection: each thread keeps its 16 distances + local argmin
// key in registers. Per pass only the owner of the extracted point recomputes.
__global__ __launch_bounds__(256) void knn_kernel(const float* __restrict__ coors)
{
    __shared__ unsigned long long keys[256];
    __shared__ unsigned long long swin;
    const int tid = threadIdx.x;
    const int g = blockIdx.x;
    const int boff = g & ~(NPTS - 1);

    const float cix = coors[g*3+0], ciy = coors[g*3+1], ciz = coors[g*3+2];

    float dv[16];
    #pragma unroll
    for (int s = 0; s < 16; s++) {
        const int j = tid + s*256;
        const int r = boff + j;
        float dx = cix - coors[r*3+0];
        float dy = ciy - coors[r*3+1];
        float dz = ciz - coors[r*3+2];
        dv[s] = dx*dx + dy*dy + dz*dz;
    }
    unsigned long long lb = 0xFFFFFFFFFFFFFFFFull;
    #pragma unroll
    for (int s = 0; s < 16; s++) {
        unsigned long long key =
            ((unsigned long long)__float_as_uint(dv[s]) << 32) | (unsigned)(tid + s*256);
        if (key < lb) lb = key;
    }

    for (int k = 0; k < KNN_K; k++) {
        keys[tid] = lb;
        __syncthreads();
        if (tid < 32) {
            unsigned long long v = keys[tid];
            #pragma unroll
            for (int o = 1; o < 8; o++) {
                unsigned long long t = keys[tid + o*32];
                if (t < v) v = t;
            }
            #pragma unroll
            for (int off = 16; off; off >>= 1) {
                unsigned long long o = __shfl_xor_sync(0xffffffffu, v, off);
                if (o < v) v = o;
            }
            if (tid == 0) {
                swin = v;
                d_idx[g*KNN_K + k] = (int)(v & 0xFFFFFFFFull);
            }
        }
        __syncthreads();
        const int wj = (int)(swin & 0xFFFFFFFFull);
        if ((wj & 255) == tid) {
            dv[wj >> 8] = __int_as_float(0x7F800000);
            lb = 0xFFFFFFFFFFFFFFFFull;
            #pragma unroll
            for (int s = 0; s < 16; s++) {
                unsigned long long key =
                    ((unsigned long long)__float_as_uint(dv[s]) << 32) | (unsigned)(tid + s*256);
                if (key < lb) lb = key;
            }
        }
    }
}

// ------------------------------ tiled GEMM 128x64 (FFMA2) ----------------------
__global__ __launch_bounds__(256) void gemm_k(
    const float* __restrict__ X, int ldx,
    const float* __restrict__ W, int ldw,
    const float* __restrict__ bias,
    const float* __restrict__ resid, int ldr,
    float* __restrict__ Y, int ldy,
    int M, int N, int K, int act)
{
    __shared__ float Xs[16*128];
    __shared__ float Ws[16*64];
    const int tid = threadIdx.x;
    const int tm = tid >> 4, tn = tid & 15;
    const int m0 = blockIdx.y * 128, n0 = blockIdx.x * 64;

    unsigned long long acc2[8][2];
    #pragma unroll
    for (int i = 0; i < 8; i++) { acc2[i][0] = 0ull; acc2[i][1] = 0ull; }

    for (int k0 = 0; k0 < K; k0 += 16) {
        #pragma unroll
        for (int i = 0; i < 8; i++) {
            int idx = tid + i*256;
            int m = idx >> 4, kk = idx & 15;
            Xs[kk*128 + (m ^ (kk*2))] = X[(size_t)(m0 + m) * ldx + k0 + kk];
        }
        #pragma unroll
        for (int i = 0; i < 4; i++) {
            int idx = tid + i*256;
            int kk = idx >> 6, n = idx & 63;
            int nn = n0 + n;
            Ws[kk*64 + n] = (nn < N) ? W[(size_t)(k0 + kk) * ldw + nn] : 0.f;
        }
        __syncthreads();
        #pragma unroll
        for (int kk = 0; kk < 16; kk++) {
            float a[8];
            #pragma unroll
            for (int i = 0; i < 8; i++) a[i] = Xs[kk*128 + ((tm*8 + i) ^ (kk*2))];
            float4 bv = *(const float4*)(Ws + kk*64 + tn*4);
            const unsigned long long bp0 = pk2(bv.x, bv.y);
            const unsigned long long bp1 = pk2(bv.z, bv.w);
            #pragma unroll
            for (int i = 0; i < 8; i++) {
                const unsigned long long ap = pk2(a[i], a[i]);
                acc2[i][0] = fma2(ap, bp0, acc2[i][0]);
                acc2[i][1] = fma2(ap, bp1, acc2[i][1]);
            }
        }
        __syncthreads();
    }

    #pragma unroll
    for (int i = 0; i < 8; i++) {
        int r = m0 + tm*8 + i;
        float vj[4];
        upk2(acc2[i][0], vj[0], vj[1]);
        upk2(acc2[i][1], vj[2], vj[3]);
        #pragma unroll
        for (int j = 0; j < 4; j++) {
            int c = n0 + tn*4 + j;
            if (c < N) {
                float v = vj[j];
                if (bias)  v += bias[c];
                if (act)   v = siluf(v);
                if (resid) v += resid[(size_t)r * ldr + c];
                Y[(size_t)r * ldy + c] = v;
            }
        }
    }
}

// ------------------------------ fused edge kernel ------------------------------
// 256 threads = 8 warps; 8 nodes/block; warp owns a node; 16 groups of 2 edges.
__global__ __launch_bounds__(256, 2) void edge_kernel(
    const float* __restrict__ coors,
    const float* __restrict__ be2,   // 16
    const float* __restrict__ Wc1,   // 16 x 64
    const float* __restrict__ bc1,   // 64
    const float* __restrict__ Wc2,   // 64
    const float* __restrict__ bc2,   // 1
    float* __restrict__ out_coors)   // NG x 3
{
    __shared__ float sA[NPB*EHP];
    __shared__ float sWc1[16*64];
    __shared__ float sWc2[64];
    __shared__ float sbc1[64];
    __shared__ float sbe2[16];
    __shared__ float sfe[NPB*32*9];
    __shared__ float srel[NPB*32*3];
    __shared__ int   sj[NPB*32];

    const int tid  = threadIdx.x;
    const int w    = tid >> 5;
    const int lane = tid & 31;

    {
        const int g0 = blockIdx.x * NPB;
        for (int i = tid; i < NPB*EHP; i += 256)
            sA[i] = d_A[(size_t)g0*EHP + i];
    }
    for (int i = tid; i < 1024; i += 256) sWc1[i] = Wc1[i];
    if (tid < 64) sWc2[tid] = Wc2[tid];
    if (tid < 64) sbc1[tid] = bc1[tid];
    if (tid < 16) sbe2[tid] = be2[tid];

    const int g = blockIdx.x * NPB + w;
    const int boff = g & ~(NPTS - 1);
    const float cix = coors[g*3+0], ciy = coors[g*3+1], ciz = coors[g*3+2];
    const float bc2v = bc2[0];

    // precompute all 32 edges' fourier features + rel coords (one lane each)
    {
        const int j = d_idx[g*KNN_K + lane];
        sj[w*32 + lane] = j;
        const int r = boff + j;
        float rx = cix - coors[r*3+0];
        float ry = ciy - coors[r*3+1];
        float rz = ciz - coors[r*3+2];
        float d  = rx*rx + ry*ry + rz*rz;
        float* fp = sfe + (w*32 + lane)*9;
        float s, c;
        sincosf(d,        &s, &c); fp[0] = s; fp[4] = c;
        sincosf(d*0.5f,   &s, &c); fp[1] = s; fp[5] = c;
        sincosf(d*0.25f,  &s, &c); fp[2] = s; fp[6] = c;
        sincosf(d*0.125f, &s, &c); fp[3] = s; fp[7] = c;
        fp[8] = d;
        float* rp = srel + (w*32 + lane)*3;
        rp[0] = rx; rp[1] = ry; rp[2] = rz;
    }
    __syncthreads();

    const int tcomp = lane & 15;      // output component this lane will own
    float misum_loc = 0.f;
    float cax = 0.f, cay = 0.f, caz = 0.f;

    #pragma unroll 1
    for (int grp = 0; grp < 16; grp++) {
        const int e0 = grp*2;
        unsigned long long fe01[9];
        #pragma unroll
        for (int t = 0; t < 9; t++)
            fe01[t] = pk2(sfe[(w*32 + e0)*9 + t], sfe[(w*32 + e0 + 1)*9 + t]);
        const float* B0 = d_Bf + (size_t)(boff + sj[w*32 + e0    ]) * EHP;
        const float* B1 = d_Bf + (size_t)(boff + sj[w*32 + e0 + 1]) * EHP;

        unsigned long long acc0[8], acc1[8];
        #pragma unroll
        for (int p = 0; p < 8; p++) { acc0[p] = 0ull; acc1[p] = 0ull; }

        // software-pipelined B loads (L2-latency hiding)
        float b0 = B0[lane], b1 = B1[lane];

        #pragma unroll 1
        for (int it = 0; it < 17; it++) {
            const int k = it*32 + lane;
            float nb0, nb1;
            if (it < 16) { nb0 = B0[k + 32]; nb1 = B1[k + 32]; }
            const float a = sA[w*EHP + k];
            unsigned long long f01 = pk2(a + b0, a + b1);
            #pragma unroll
            for (int t = 0; t < 9; t++) {
                const float wv = d_W1fp[t*EHP + k];
                f01 = fma2(fe01[t], pk2(wv, wv), f01);
            }
            float f0, f1; upk2(f01, f0, f1);
            const float h0 = siluf(f0);
            const float h1 = siluf(f1);
            const unsigned long long h0p = pk2(h0, h0);
            const unsigned long long h1p = pk2(h1, h1);
            const ulonglong2* wp = (const ulonglong2*)(d_We2p + (size_t)k*16);
            #pragma unroll
            for (int c = 0; c < 4; c++) {
                ulonglong2 w2 = wp[c];
                acc0[c*2]   = fma2(h0p, w2.x, acc0[c*2]);
                acc0[c*2+1] = fma2(h0p, w2.y, acc0[c*2+1]);
                acc1[c*2]   = fma2(h1p, w2.x, acc1[c*2]);
                acc1[c*2+1] = fma2(h1p, w2.y, acc1[c*2+1]);
            }
            b0 = nb0; b1 = nb1;
        }

        // reduce-scatter: final lane L holds m[L&15] of edge e0 + (L>>4)
        unsigned long long a8[8];
        #pragma unroll
        for (int p = 0; p < 8; p++) {
            unsigned long long s = (lane & 16) ? acc0[p] : acc1[p];
            unsigned long long r = __shfl_xor_sync(0xffffffffu, s, 16);
            a8[p] = add2((lane & 16) ? acc1[p] : acc0[p], r);
        }
        unsigned long long a4[4];
        #pragma unroll
        for (int q = 0; q < 4; q++) {
            unsigned long long s = (lane & 8) ? a8[q] : a8[q+4];
            unsigned long long r = __shfl_xor_sync(0xffffffffu, s, 8);
            a4[q] = add2((lane & 8) ? a8[q+4] : a8[q], r);
        }
        unsigned long long a2[2];
        #pragma unroll
        for (int q = 0; q < 2; q++) {
            unsigned long long s = (lane & 4) ? a4[q] : a4[q+2];
            unsigned long long r = __shfl_xor_sync(0xffffffffu, s, 4);
            a2[q] = add2((lane & 4) ? a4[q+2] : a4[q], r);
        }
        unsigned long long a1;
        {
            unsigned long long s = (lane & 2) ? a2[0] : a2[1];
            unsigned long long r = __shfl_xor_sync(0xffffffffu, s, 2);
            a1 = add2((lane & 2) ? a2[1] : a2[0], r);
        }
        float lo, hi; upk2(a1, lo, hi);
        {
            float s = (lane & 1) ? lo : hi;
            float r = __shfl_xor_sync(0xffffffffu, s, 1);
            lo = ((lane & 1) ? hi : lo) + r;
        }
        // lo = raw m component tcomp of this half's edge
        const float mv = siluf(lo + sbe2[tcomp]);
        misum_loc += mv;

        // rebuild full m[16] for own edge via idx-shuffle
        float mf[16];
        #pragma unroll
        for (int t = 0; t < MDIM; t++)
            mf[t] = __shfl_sync(0xffffffffu, mv, (lane & 16) | t);

        // coors MLP: each lane handles 4 hidden cols of its own edge
        float4 hb = *(const float4*)(sbc1 + tcomp*4);
        float h0 = hb.x, h1 = hb.y, h2 = hb.z, h3 = hb.w;
        #pragma unroll
        for (int t = 0; t < MDIM; t++) {
            float4 wv4 = *(const float4*)(sWc1 + t*64 + tcomp*4);
            h0 = fmaf(mf[t], wv4.x, h0);
            h1 = fmaf(mf[t], wv4.y, h1);
            h2 = fmaf(mf[t], wv4.z, h2);
            h3 = fmaf(mf[t], wv4.w, h3);
        }
        float4 c2 = *(const float4*)(sWc2 + tcomp*4);
        float wv = siluf(h0)*c2.x + siluf(h1)*c2.y + siluf(h2)*c2.z + siluf(h3)*c2.w;
        #pragma unroll
        for (int off = 8; off; off >>= 1)
            wv += __shfl_xor_sync(0xffffffffu, wv, off);
        const float we = wv + bc2v;
        const int eIdx = e0 + (lane >> 4);
        const float* rp = srel + (w*32 + eIdx)*3;
        cax = fmaf(we, rp[0], cax);
        cay = fmaf(we, rp[1], cay);
        caz = fmaf(we, rp[2], caz);
    }

    // combine halves
    cax += __shfl_xor_sync(0xffffffffu, cax, 16);
    cay += __shfl_xor_sync(0xffffffffu, cay, 16);
    caz += __shfl_xor_sync(0xffffffffu, caz, 16);
    float mtot = misum_loc + __shfl_xor_sync(0xffffffffu, misum_loc, 16);
    if (lane < 16) d_mi[(size_t)g*MDIM + lane] = mtot;
    if (lane == 0) {
        out_coors[g*3+0] = cax + cix;
        out_coors[g*3+1] = cay + ciy;
        out_coors[g*3+2] = caz + ciz;
    }
}

// build concat(feats, m_i) -> d_nodein
__global__ void nodein_kernel(const float* __restrict__ feats)
{
    int i = blockIdx.x * blockDim.x + threadIdx.x;
    if (i < NG * NODE_IN) {
        int gg = i / NODE_IN, c = i - gg * NODE_IN;
        d_nodein[i] = (c < DIM) ? feats[(size_t)gg*DIM + c]
                                : d_mi[(size_t)gg*MDIM + (c - DIM)];
    }
}

// ------------------------------ launch ----------------------------------------
extern "C" void kernel_launch(void* const* d_in, const int* in_sizes, int n_in,
                              void* d_out, int out_size)
{
    const float* feats = (const float*)d_in[0];
    const float* coors = (const float*)d_in[1];
    const float* We1   = (const float*)d_in[2];
    const float* be1   = (const float*)d_in[3];
    const float* We2   = (const float*)d_in[4];
    const float* be2   = (const float*)d_in[5];
    const float* Wc1   = (const float*)d_in[6];
    const float* bc1   = (const float*)d_in[7];
    const float* Wc2   = (const float*)d_in[8];
    const float* bc2   = (const float*)d_in[9];
    const float* Wn1   = (const float*)d_in[10];
    const float* bn1   = (const float*)d_in[11];
    const float* Wn2   = (const float*)d_in[12];
    const float* bn2   = (const float*)d_in[13];

    float* out_nodes = (float*)d_out;
    float* out_coors = out_nodes + (size_t)NG * DIM;

    float *pA, *pB, *pNI, *pH;
    cudaGetSymbolAddress((void**)&pA,  d_A);
    cudaGetSymbolAddress((void**)&pB,  d_Bf);
    cudaGetSymbolAddress((void**)&pNI, d_nodein);
    cudaGetSymbolAddress((void**)&pH,  d_h);

    // 0. padded weight copies
    pad_weights_kernel<<<(EHP*16 + 255)/256, 256>>>(We1, We2);

    // 1. KNN
    knn_kernel<<<NG, 256>>>(coors);

    // 2. A = feats @ We1[0:128] + be1 ; B = feats @ We1[128:256]   (ld-out = 544)
    {
        dim3 grid((EH + 63) / 64, NG / 128);
        gemm_k<<<grid, 256>>>(feats, DIM, We1,          EH, be1,     nullptr, 0, pA, EHP, NG, EH, DIM, 0);
        gemm_k<<<grid, 256>>>(feats, DIM, We1 + 128*EH, EH, nullptr, nullptr, 0, pB, EHP, NG, EH, DIM, 0);
    }

    // 3. fused edge kernel: m_i + coors_out
    edge_kernel<<<NG / NPB, 256>>>(coors, be2, Wc1, bc1, Wc2, bc2, out_coors);

    // 4. node MLP
    nodein_kernel<<<(NG*NODE_IN + 255)/256, 256>>>(feats);
    {
        dim3 g1(NODE_H / 64, NG / 128);
        gemm_k<<<g1, 256>>>(pNI, NODE_IN, Wn1, NODE_H, bn1, nullptr, 0, pH, NODE_H, NG, NODE_H, NODE_IN, 1);
        dim3 g2(DIM / 64, NG / 128);
        gemm_k<<<g2, 256>>>(pH, NODE_H, Wn2, DIM, bn2, feats, DIM, out_nodes, DIM, NG, DIM, NODE_H, 0);
    }
}

// round 5
// speedup vs baseline: 1.4443x; 1.4443x over previous
#include <cuda_runtime.h>
#include <cuda_bf16.h>
#include <math.h>

// Problem constants
#define BATCH 2
#define NPTS  4096
#define NG    (BATCH*NPTS)     // 8192 nodes total
#define DIM   128
#define MDIM  16
#define KNN_K 32
#define EH    530              // edge hidden dim (2*265)
#define EHP   544              // padded to 17*32
#define NODE_IN 144            // DIM + MDIM
#define NODE_H  256
#define NPB   8                // nodes per edge-kernel block

// -------------------- scratch (static device globals; no allocation) ----------
__device__ float d_A [NG * EHP];      // feats @ We1[0:128] + be1   (cols 530..543 stay 0)
__device__ float d_Bf[NG * EHP];      // feats @ We1[128:256]       (cols 530..543 stay 0)
__device__ int   d_idx[NG * KNN_K];
__device__ float d_mi [NG * MDIM];
__device__ float d_nodein[NG * NODE_IN];
__device__ float d_h  [NG * NODE_H];
__device__ float d_W1fp[9 * EHP];     // zero-padded fourier rows of We1 (k-minor)

__device__ __forceinline__ float siluf(float x) {
    return x / (1.0f + __expf(-x));
}

// ---------------- packed f32x2 helpers (Blackwell FFMA2 path) ------------------
__device__ __forceinline__ unsigned long long pk2(float lo, float hi) {
    unsigned long long r; asm("mov.b64 %0, {%1,%2};" : "=l"(r) : "f"(lo), "f"(hi)); return r;
}
__device__ __forceinline__ void upk2(unsigned long long v, float &lo, float &hi) {
    asm("mov.b64 {%0,%1}, %2;" : "=f"(lo), "=f"(hi) : "l"(v));
}
__device__ __forceinline__ unsigned long long fma2(unsigned long long a,
                                                   unsigned long long b,
                                                   unsigned long long c) {
    unsigned long long d;
    asm("fma.rn.f32x2 %0, %1, %2, %3;" : "=l"(d) : "l"(a), "l"(b), "l"(c));
    return d;
}
__device__ __forceinline__ unsigned long long add2(unsigned long long a,
                                                   unsigned long long b) {
    unsigned long long d;
    asm("add.rn.f32x2 %0, %1, %2;" : "=l"(d) : "l"(a), "l"(b));
    return d;
}

// ---------------------- pad fourier weight rows --------------------------------
__global__ void pad_weights_kernel(const float* __restrict__ We1)
{
    int i = blockIdx.x * blockDim.x + threadIdx.x;
    if (i < 9 * EHP) {
        int t = i / EHP, k = i - t * EHP;
        d_W1fp[i] = (k < EH) ? We1[(256 + t) * EH + k] : 0.f;
    }
}

// ------------------------------ KNN -------------------------------------------
// Cached-candidate selection: each thread keeps its 16 distances + local argmin
// key in registers. Per pass only the owner of the extracted point recomputes.
__global__ __launch_bounds__(256) void knn_kernel(const float* __restrict__ coors)
{
    __shared__ unsigned long long keys[256];
    __shared__ unsigned long long swin;
    const int tid = threadIdx.x;
    const int g = blockIdx.x;
    const int boff = g & ~(NPTS - 1);

    const float cix = coors[g*3+0], ciy = coors[g*3+1], ciz = coors[g*3+2];

    float dv[16];
    #pragma unroll
    for (int s = 0; s < 16; s++) {
        const int j = tid + s*256;
        const int r = boff + j;
        float dx = cix - coors[r*3+0];
        float dy = ciy - coors[r*3+1];
        float dz = ciz - coors[r*3+2];
        dv[s] = dx*dx + dy*dy + dz*dz;
    }
    unsigned long long lb = 0xFFFFFFFFFFFFFFFFull;
    #pragma unroll
    for (int s = 0; s < 16; s++) {
        unsigned long long key =
            ((unsigned long long)__float_as_uint(dv[s]) << 32) | (unsigned)(tid + s*256);
        if (key < lb) lb = key;
    }

    for (int k = 0; k < KNN_K; k++) {
        keys[tid] = lb;
        __syncthreads();
        if (tid < 32) {
            unsigned long long v = keys[tid];
            #pragma unroll
            for (int o = 1; o < 8; o++) {
                unsigned long long t = keys[tid + o*32];
                if (t < v) v = t;
            }
            #pragma unroll
            for (int off = 16; off; off >>= 1) {
                unsigned long long o = __shfl_xor_sync(0xffffffffu, v, off);
                if (o < v) v = o;
            }
            if (tid == 0) {
                swin = v;
                d_idx[g*KNN_K + k] = (int)(v & 0xFFFFFFFFull);
            }
        }
        __syncthreads();
        const int wj = (int)(swin & 0xFFFFFFFFull);
        if ((wj & 255) == tid) {
            dv[wj >> 8] = __int_as_float(0x7F800000);
            lb = 0xFFFFFFFFFFFFFFFFull;
            #pragma unroll
            for (int s = 0; s < 16; s++) {
                unsigned long long key =
                    ((unsigned long long)__float_as_uint(dv[s]) << 32) | (unsigned)(tid + s*256);
                if (key < lb) lb = key;
            }
        }
    }
}

// ------------------------------ tiled GEMM 128x64 (FFMA2) ----------------------
__global__ __launch_bounds__(256) void gemm_k(
    const float* __restrict__ X, int ldx,
    const float* __restrict__ W, int ldw,
    const float* __restrict__ bias,
    const float* __restrict__ resid, int ldr,
    float* __restrict__ Y, int ldy,
    int M, int N, int K, int act)
{
    __shared__ float Xs[16*128];
    __shared__ float Ws[16*64];
    const int tid = threadIdx.x;
    const int tm = tid >> 4, tn = tid & 15;
    const int m0 = blockIdx.y * 128, n0 = blockIdx.x * 64;

    unsigned long long acc2[8][2];
    #pragma unroll
    for (int i = 0; i < 8; i++) { acc2[i][0] = 0ull; acc2[i][1] = 0ull; }

    for (int k0 = 0; k0 < K; k0 += 16) {
        #pragma unroll
        for (int i = 0; i < 8; i++) {
            int idx = tid + i*256;
            int m = idx >> 4, kk = idx & 15;
            Xs[kk*128 + (m ^ (kk*2))] = X[(size_t)(m0 + m) * ldx + k0 + kk];
        }
        #pragma unroll
        for (int i = 0; i < 4; i++) {
            int idx = tid + i*256;
            int kk = idx >> 6, n = idx & 63;
            int nn = n0 + n;
            Ws[kk*64 + n] = (nn < N) ? W[(size_t)(k0 + kk) * ldw + nn] : 0.f;
        }
        __syncthreads();
        #pragma unroll
        for (int kk = 0; kk < 16; kk++) {
            float a[8];
            #pragma unroll
            for (int i = 0; i < 8; i++) a[i] = Xs[kk*128 + ((tm*8 + i) ^ (kk*2))];
            float4 bv = *(const float4*)(Ws + kk*64 + tn*4);
            const unsigned long long bp0 = pk2(bv.x, bv.y);
            const unsigned long long bp1 = pk2(bv.z, bv.w);
            #pragma unroll
            for (int i = 0; i < 8; i++) {
                const unsigned long long ap = pk2(a[i], a[i]);
                acc2[i][0] = fma2(ap, bp0, acc2[i][0]);
                acc2[i][1] = fma2(ap, bp1, acc2[i][1]);
            }
        }
        __syncthreads();
    }

    #pragma unroll
    for (int i = 0; i < 8; i++) {
        int r = m0 + tm*8 + i;
        float vj[4];
        upk2(acc2[i][0], vj[0], vj[1]);
        upk2(acc2[i][1], vj[2], vj[3]);
        #pragma unroll
        for (int j = 0; j < 4; j++) {
            int c = n0 + tn*4 + j;
            if (c < N) {
                float v = vj[j];
                if (bias)  v += bias[c];
                if (act)   v = siluf(v);
                if (resid) v += resid[(size_t)r * ldr + c];
                Y[(size_t)r * ldy + c] = v;
            }
        }
    }
}

// ------------------------------ fused edge kernel ------------------------------
// 256 threads = 8 warps; 8 nodes/block; warp owns a node; 16 groups of 2 edges.
// We2 staged in smem t-major (conflict-free scalar LDS, 1 wavefront/load).
__global__ __launch_bounds__(256, 2) void edge_kernel(
    const float* __restrict__ coors,
    const float* __restrict__ We2,   // 530 x 16
    const float* __restrict__ be2,   // 16
    const float* __restrict__ Wc1,   // 16 x 64
    const float* __restrict__ bc1,   // 64
    const float* __restrict__ Wc2,   // 64
    const float* __restrict__ bc2,   // 1
    float* __restrict__ out_coors)   // NG x 3
{
    extern __shared__ float sm[];
    float* sWe2T = sm;                      // [16][EHP] t-major
    float* sA    = sWe2T + 16*EHP;          // [NPB][EHP]
    float* sWc1  = sA    + NPB*EHP;         // [16][64]
    float* sWc2  = sWc1  + 1024;            // [64]
    float* sbc1  = sWc2  + 64;              // [64]
    float* sbe2  = sbc1  + 64;              // [16]
    float* sfe   = sbe2  + 16;              // [NPB][32][9]
    float* srel  = sfe   + NPB*32*9;        // [NPB][32][3]
    int*   sj    = (int*)(srel + NPB*32*3); // [NPB][32]

    const int tid  = threadIdx.x;
    const int w    = tid >> 5;
    const int lane = tid & 31;

    for (int i = tid; i < 16*EHP; i += 256) {
        int t = i / EHP, k = i - t*EHP;
        sWe2T[i] = (k < EH) ? We2[k*16 + t] : 0.f;
    }
    {
        const int g0 = blockIdx.x * NPB;
        for (int i = tid; i < NPB*EHP; i += 256)
            sA[i] = d_A[(size_t)g0*EHP + i];
    }
    for (int i = tid; i < 1024; i += 256) sWc1[i] = Wc1[i];
    if (tid < 64) sWc2[tid] = Wc2[tid];
    if (tid < 64) sbc1[tid] = bc1[tid];
    if (tid < 16) sbe2[tid] = be2[tid];

    const int g = blockIdx.x * NPB + w;
    const int boff = g & ~(NPTS - 1);
    const float cix = coors[g*3+0], ciy = coors[g*3+1], ciz = coors[g*3+2];
    const float bc2v = bc2[0];

    // precompute all 32 edges' fourier features + rel coords (one lane each)
    {
        const int j = d_idx[g*KNN_K + lane];
        sj[w*32 + lane] = j;
        const int r = boff + j;
        float rx = cix - coors[r*3+0];
        float ry = ciy - coors[r*3+1];
        float rz = ciz - coors[r*3+2];
        float d  = rx*rx + ry*ry + rz*rz;
        float* fp = sfe + (w*32 + lane)*9;
        float s, c;
        sincosf(d,        &s, &c); fp[0] = s; fp[4] = c;
        sincosf(d*0.5f,   &s, &c); fp[1] = s; fp[5] = c;
        sincosf(d*0.25f,  &s, &c); fp[2] = s; fp[6] = c;
        sincosf(d*0.125f, &s, &c); fp[3] = s; fp[7] = c;
        fp[8] = d;
        float* rp = srel + (w*32 + lane)*3;
        rp[0] = rx; rp[1] = ry; rp[2] = rz;
    }
    __syncthreads();

    const int tcomp = lane & 15;      // output component this lane will own
    float misum_loc = 0.f;
    float cax = 0.f, cay = 0.f, caz = 0.f;

    #pragma unroll 1
    for (int grp = 0; grp < 16; grp++) {
        const int e0 = grp*2;
        unsigned long long fe01[9];
        #pragma unroll
        for (int t = 0; t < 9; t++)
            fe01[t] = pk2(sfe[(w*32 + e0)*9 + t], sfe[(w*32 + e0 + 1)*9 + t]);
        const float* B0 = d_Bf + (size_t)(boff + sj[w*32 + e0    ]) * EHP;
        const float* B1 = d_Bf + (size_t)(boff + sj[w*32 + e0 + 1]) * EHP;

        // acc01[t] = packed (edge0, edge1) partial for output component t
        unsigned long long acc01[16];
        #pragma unroll
        for (int t = 0; t < 16; t++) acc01[t] = 0ull;

        float b0 = B0[lane], b1 = B1[lane];

        #pragma unroll 1
        for (int it = 0; it < 17; it++) {
            const int k = it*32 + lane;
            float nb0, nb1;
            if (it < 16) { nb0 = B0[k + 32]; nb1 = B1[k + 32]; }
            const float a = sA[w*EHP + k];
            unsigned long long f01 = pk2(a + b0, a + b1);
            #pragma unroll
            for (int t = 0; t < 9; t++) {
                const float wv = d_W1fp[t*EHP + k];
                f01 = fma2(fe01[t], pk2(wv, wv), f01);
            }
            float f0, f1; upk2(f01, f0, f1);
            const unsigned long long h01 = pk2(siluf(f0), siluf(f1));
            #pragma unroll
            for (int t = 0; t < 16; t++) {
                const float wv = sWe2T[t*EHP + k];
                acc01[t] = fma2(h01, pk2(wv, wv), acc01[t]);
            }
            b0 = nb0; b1 = nb1;
        }

        // t-scatter reduce over lanes: lane L ends with t = L & 15 (both edges packed)
        unsigned long long a8[8];
        #pragma unroll
        for (int q = 0; q < 8; q++) {
            unsigned long long s = (lane & 8) ? acc01[q] : acc01[q+8];
            unsigned long long r = __shfl_xor_sync(0xffffffffu, s, 8);
            a8[q] = add2((lane & 8) ? acc01[q+8] : acc01[q], r);
        }
        unsigned long long a4[4];
        #pragma unroll
        for (int q = 0; q < 4; q++) {
            unsigned long long s = (lane & 4) ? a8[q] : a8[q+4];
            unsigned long long r = __shfl_xor_sync(0xffffffffu, s, 4);
            a4[q] = add2((lane & 4) ? a8[q+4] : a8[q], r);
        }
        unsigned long long a2[2];
        #pragma unroll
        for (int q = 0; q < 2; q++) {
            unsigned long long s = (lane & 2) ? a2[0] : 0ull; // placeholder, replaced below
            (void)s;
            unsigned long long ss = (lane & 2) ? a4[q] : a4[q+2];
            unsigned long long r = __shfl_xor_sync(0xffffffffu, ss, 2);
            a2[q] = add2((lane & 2) ? a4[q+2] : a4[q], r);
        }
        unsigned long long a1;
        {
            unsigned long long ss = (lane & 1) ? a2[0] : a2[1];
            unsigned long long r = __shfl_xor_sync(0xffffffffu, ss, 1);
            a1 = add2((lane & 1) ? a2[1] : a2[0], r);
        }
        // final k-fold across half-warps (same t, both halves)
        {
            unsigned long long r = __shfl_xor_sync(0xffffffffu, a1, 16);
            a1 = add2(a1, r);
        }
        float vlo, vhi; upk2(a1, vlo, vhi);
        // lanes 0-15 own edge e0 (lo), lanes 16-31 own edge e0+1 (hi)
        const float rawm = (lane & 16) ? vhi : vlo;
        const float mv = siluf(rawm + sbe2[tcomp]);
        misum_loc += mv;

        // rebuild full m[16] for own edge via idx-shuffle
        float mf[16];
        #pragma unroll
        for (int t = 0; t < MDIM; t++)
            mf[t] = __shfl_sync(0xffffffffu, mv, (lane & 16) | t);

        // coors MLP: each lane handles 4 hidden cols of its own edge
        float4 hb = *(const float4*)(sbc1 + tcomp*4);
        float h0 = hb.x, h1 = hb.y, h2 = hb.z, h3 = hb.w;
        #pragma unroll
        for (int t = 0; t < MDIM; t++) {
            float4 wv4 = *(const float4*)(sWc1 + t*64 + tcomp*4);
            h0 = fmaf(mf[t], wv4.x, h0);
            h1 = fmaf(mf[t], wv4.y, h1);
            h2 = fmaf(mf[t], wv4.z, h2);
            h3 = fmaf(mf[t], wv4.w, h3);
        }
        float4 c2 = *(const float4*)(sWc2 + tcomp*4);
        float wv = siluf(h0)*c2.x + siluf(h1)*c2.y + siluf(h2)*c2.z + siluf(h3)*c2.w;
        #pragma unroll
        for (int off = 8; off; off >>= 1)
            wv += __shfl_xor_sync(0xffffffffu, wv, off);
        const float we = wv + bc2v;
        const int eIdx = e0 + (lane >> 4);
        const float* rp = srel + (w*32 + eIdx)*3;
        cax = fmaf(we, rp[0], cax);
        cay = fmaf(we, rp[1], cay);
        caz = fmaf(we, rp[2], caz);
    }

    // combine halves
    cax += __shfl_xor_sync(0xffffffffu, cax, 16);
    cay += __shfl_xor_sync(0xffffffffu, cay, 16);
    caz += __shfl_xor_sync(0xffffffffu, caz, 16);
    float mtot = misum_loc + __shfl_xor_sync(0xffffffffu, misum_loc, 16);
    if (lane < 16) d_mi[(size_t)g*MDIM + lane] = mtot;
    if (lane == 0) {
        out_coors[g*3+0] = cax + cix;
        out_coors[g*3+1] = cay + ciy;
        out_coors[g*3+2] = caz + ciz;
    }
}

// build concat(feats, m_i) -> d_nodein
__global__ void nodein_kernel(const float* __restrict__ feats)
{
    int i = blockIdx.x * blockDim.x + threadIdx.x;
    if (i < NG * NODE_IN) {
        int gg = i / NODE_IN, c = i - gg * NODE_IN;
        d_nodein[i] = (c < DIM) ? feats[(size_t)gg*DIM + c]
                                : d_mi[(size_t)gg*MDIM + (c - DIM)];
    }
}

// ------------------------------ launch ----------------------------------------
extern "C" void kernel_launch(void* const* d_in, const int* in_sizes, int n_in,
                              void* d_out, int out_size)
{
    const float* feats = (const float*)d_in[0];
    const float* coors = (const float*)d_in[1];
    const float* We1   = (const float*)d_in[2];
    const float* be1   = (const float*)d_in[3];
    const float* We2   = (const float*)d_in[4];
    const float* be2   = (const float*)d_in[5];
    const float* Wc1   = (const float*)d_in[6];
    const float* bc1   = (const float*)d_in[7];
    const float* Wc2   = (const float*)d_in[8];
    const float* bc2   = (const float*)d_in[9];
    const float* Wn1   = (const float*)d_in[10];
    const float* bn1   = (const float*)d_in[11];
    const float* Wn2   = (const float*)d_in[12];
    const float* bn2   = (const float*)d_in[13];

    float* out_nodes = (float*)d_out;
    float* out_coors = out_nodes + (size_t)NG * DIM;

    float *pA, *pB, *pNI, *pH;
    cudaGetSymbolAddress((void**)&pA,  d_A);
    cudaGetSymbolAddress((void**)&pB,  d_Bf);
    cudaGetSymbolAddress((void**)&pNI, d_nodein);
    cudaGetSymbolAddress((void**)&pH,  d_h);

    const int smem_floats = 16*EHP + NPB*EHP + 1024 + 64 + 64 + 16
                          + NPB*32*9 + NPB*32*3 + NPB*32;
    const int smem_bytes  = smem_floats * 4;
    cudaFuncSetAttribute(edge_kernel, cudaFuncAttributeMaxDynamicSharedMemorySize, smem_bytes);

    // 0. padded fourier weights
    pad_weights_kernel<<<(9*EHP + 255)/256, 256>>>(We1);

    // 1. KNN
    knn_kernel<<<NG, 256>>>(coors);

    // 2. A = feats @ We1[0:128] + be1 ; B = feats @ We1[128:256]   (ld-out = 544)
    {
        dim3 grid((EH + 63) / 64, NG / 128);
        gemm_k<<<grid, 256>>>(feats, DIM, We1,          EH, be1,     nullptr, 0, pA, EHP, NG, EH, DIM, 0);
        gemm_k<<<grid, 256>>>(feats, DIM, We1 + 128*EH, EH, nullptr, nullptr, 0, pB, EHP, NG, EH, DIM, 0);
    }

    // 3. fused edge kernel: m_i + coors_out
    edge_kernel<<<NG / NPB, 256, smem_bytes>>>(coors, We2, be2, Wc1, bc1, Wc2, bc2, out_coors);

    // 4. node MLP
    nodein_kernel<<<(NG*NODE_IN + 255)/256, 256>>>(feats);
    {
        dim3 g1(NODE_H / 64, NG / 128);
        gemm_k<<<g1, 256>>>(pNI, NODE_IN, Wn1, NODE_H, bn1, nullptr, 0, pH, NODE_H, NG, NODE_H, NODE_IN, 1);
        dim3 g2(DIM / 64, NG / 128);
        gemm_k<<<g2, 256>>>(pH, NODE_H, Wn2, DIM, bn2, feats, DIM, out_nodes, DIM, NG, DIM, NODE_H, 0);
    }
}

// round 6
// speedup vs baseline: 1.6692x; 1.1557x over previous
#include <cuda_runtime.h>
#include <cuda_bf16.h>
#include <math.h>

// Problem constants
#define BATCH 2
#define NPTS  4096
#define NG    (BATCH*NPTS)     // 8192 nodes total
#define DIM   128
#define MDIM  16
#define KNN_K 32
#define EH    530              // edge hidden dim (2*265)
#define EHP   544              // padded to 17*32
#define NODE_IN 144            // DIM + MDIM
#define NODE_H  256
#define NPB   4                // nodes per edge-kernel block (1 warp each)

// -------------------- scratch (static device globals; no allocation) ----------
__device__ float d_A [NG * EHP];      // feats @ We1[0:128] + be1   (cols 530..543 stay 0)
__device__ float d_Bf[NG * EHP];      // feats @ We1[128:256]       (cols 530..543 stay 0)
__device__ int   d_idx[NG * KNN_K];
__device__ float d_mi [NG * MDIM];
__device__ float d_nodein[NG * NODE_IN];
__device__ float d_h  [NG * NODE_H];

__device__ __forceinline__ float siluf(float x) {
    return x / (1.0f + __expf(-x));
}

// ---------------- packed f32x2 helpers (Blackwell FFMA2 path) ------------------
__device__ __forceinline__ unsigned long long pk2(float lo, float hi) {
    unsigned long long r; asm("mov.b64 %0, {%1,%2};" : "=l"(r) : "f"(lo), "f"(hi)); return r;
}
__device__ __forceinline__ void upk2(unsigned long long v, float &lo, float &hi) {
    asm("mov.b64 {%0,%1}, %2;" : "=f"(lo), "=f"(hi) : "l"(v));
}
__device__ __forceinline__ unsigned long long fma2(unsigned long long a,
                                                   unsigned long long b,
                                                   unsigned long long c) {
    unsigned long long d;
    asm("fma.rn.f32x2 %0, %1, %2, %3;" : "=l"(d) : "l"(a), "l"(b), "l"(c));
    return d;
}
__device__ __forceinline__ unsigned long long add2(unsigned long long a,
                                                   unsigned long long b) {
    unsigned long long d;
    asm("add.rn.f32x2 %0, %1, %2;" : "=l"(d) : "l"(a), "l"(b));
    return d;
}

// ------------------------------ KNN -------------------------------------------
__global__ __launch_bounds__(256) void knn_kernel(const float* __restrict__ coors)
{
    __shared__ unsigned long long keys[256];
    __shared__ unsigned long long swin;
    const int tid = threadIdx.x;
    const int g = blockIdx.x;
    const int boff = g & ~(NPTS - 1);

    const float cix = coors[g*3+0], ciy = coors[g*3+1], ciz = coors[g*3+2];

    float dv[16];
    #pragma unroll
    for (int s = 0; s < 16; s++) {
        const int j = tid + s*256;
        const int r = boff + j;
        float dx = cix - coors[r*3+0];
        float dy = ciy - coors[r*3+1];
        float dz = ciz - coors[r*3+2];
        dv[s] = dx*dx + dy*dy + dz*dz;
    }
    unsigned long long lb = 0xFFFFFFFFFFFFFFFFull;
    #pragma unroll
    for (int s = 0; s < 16; s++) {
        unsigned long long key =
            ((unsigned long long)__float_as_uint(dv[s]) << 32) | (unsigned)(tid + s*256);
        if (key < lb) lb = key;
    }

    for (int k = 0; k < KNN_K; k++) {
        keys[tid] = lb;
        __syncthreads();
        if (tid < 32) {
            unsigned long long v = keys[tid];
            #pragma unroll
            for (int o = 1; o < 8; o++) {
                unsigned long long t = keys[tid + o*32];
                if (t < v) v = t;
            }
            #pragma unroll
            for (int off = 16; off; off >>= 1) {
                unsigned long long o = __shfl_xor_sync(0xffffffffu, v, off);
                if (o < v) v = o;
            }
            if (tid == 0) {
                swin = v;
                d_idx[g*KNN_K + k] = (int)(v & 0xFFFFFFFFull);
            }
        }
        __syncthreads();
        const int wj = (int)(swin & 0xFFFFFFFFull);
        if ((wj & 255) == tid) {
            dv[wj >> 8] = __int_as_float(0x7F800000);
            lb = 0xFFFFFFFFFFFFFFFFull;
            #pragma unroll
            for (int s = 0; s < 16; s++) {
                unsigned long long key =
                    ((unsigned long long)__float_as_uint(dv[s]) << 32) | (unsigned)(tid + s*256);
                if (key < lb) lb = key;
            }
        }
    }
}

// ------------------------------ tiled GEMM 128x64 (FFMA2) ----------------------
__global__ __launch_bounds__(256) void gemm_k(
    const float* __restrict__ X, int ldx,
    const float* __restrict__ W, int ldw,
    const float* __restrict__ bias,
    const float* __restrict__ resid, int ldr,
    float* __restrict__ Y, int ldy,
    int M, int N, int K, int act)
{
    __shared__ float Xs[16*128];
    __shared__ float Ws[16*64];
    const int tid = threadIdx.x;
    const int tm = tid >> 4, tn = tid & 15;
    const int m0 = blockIdx.y * 128, n0 = blockIdx.x * 64;

    unsigned long long acc2[8][2];
    #pragma unroll
    for (int i = 0; i < 8; i++) { acc2[i][0] = 0ull; acc2[i][1] = 0ull; }

    for (int k0 = 0; k0 < K; k0 += 16) {
        #pragma unroll
        for (int i = 0; i < 8; i++) {
            int idx = tid + i*256;
            int m = idx >> 4, kk = idx & 15;
            Xs[kk*128 + (m ^ (kk*2))] = X[(size_t)(m0 + m) * ldx + k0 + kk];
        }
        #pragma unroll
        for (int i = 0; i < 4; i++) {
            int idx = tid + i*256;
            int kk = idx >> 6, n = idx & 63;
            int nn = n0 + n;
            Ws[kk*64 + n] = (nn < N) ? W[(size_t)(k0 + kk) * ldw + nn] : 0.f;
        }
        __syncthreads();
        #pragma unroll
        for (int kk = 0; kk < 16; kk++) {
            float a[8];
            #pragma unroll
            for (int i = 0; i < 8; i++) a[i] = Xs[kk*128 + ((tm*8 + i) ^ (kk*2))];
            float4 bv = *(const float4*)(Ws + kk*64 + tn*4);
            const unsigned long long bp0 = pk2(bv.x, bv.y);
            const unsigned long long bp1 = pk2(bv.z, bv.w);
            #pragma unroll
            for (int i = 0; i < 8; i++) {
                const unsigned long long ap = pk2(a[i], a[i]);
                acc2[i][0] = fma2(ap, bp0, acc2[i][0]);
                acc2[i][1] = fma2(ap, bp1, acc2[i][1]);
            }
        }
        __syncthreads();
    }

    #pragma unroll
    for (int i = 0; i < 8; i++) {
        int r = m0 + tm*8 + i;
        float vj[4];
        upk2(acc2[i][0], vj[0], vj[1]);
        upk2(acc2[i][1], vj[2], vj[3]);
        #pragma unroll
        for (int j = 0; j < 4; j++) {
            int c = n0 + tn*4 + j;
            if (c < N) {
                float v = vj[j];
                if (bias)  v += bias[c];
                if (act)   v = siluf(v);
                if (resid) v += resid[(size_t)r * ldr + c];
                Y[(size_t)r * ldy + c] = v;
            }
        }
    }
}

// ------------------------------ fused edge kernel ------------------------------
// 128 threads = 4 warps; 4 nodes/block; warp owns a node; 8 groups of 4 edges.
__global__ __launch_bounds__(128, 3) void edge_kernel(
    const float* __restrict__ coors,
    const float* __restrict__ We1,   // 265 x 530 (rows 256..264 = fourier rows)
    const float* __restrict__ We2,   // 530 x 16
    const float* __restrict__ be2,   // 16
    const float* __restrict__ Wc1,   // 16 x 64
    const float* __restrict__ bc1,   // 64
    const float* __restrict__ Wc2,   // 64
    const float* __restrict__ bc2,   // 1
    float* __restrict__ out_coors)   // NG x 3
{
    extern __shared__ float sm[];
    float* sWe2P = sm;                       // ulonglong2[4][EHP] = 8704 floats
    float* sW1f  = sWe2P + 4*EHP*4;          // [9][EHP]
    float* sA    = sW1f  + 9*EHP;            // [NPB][EHP]
    float* sWc1  = sA    + NPB*EHP;          // [16][64]
    float* sWc2  = sWc1  + 1024;             // [64]
    float* sbc1  = sWc2  + 64;               // [64]
    float* sbe2  = sbc1  + 64;               // [16]
    float* sfe   = sbe2  + 16;               // [NPB][32][9]
    float* srel  = sfe   + NPB*32*9;         // [NPB][32][3]
    int*   sj    = (int*)(srel + NPB*32*3);  // [NPB][32]

    const int tid  = threadIdx.x;
    const int w    = tid >> 5;
    const int lane = tid & 31;

    // stage We2 as packed pair quads: entry (q,k) = {(t=4q,4q+1),(4q+2,4q+3)}
    for (int i = tid; i < 4*EHP*4; i += 128) {
        int q = i / (EHP*4), r = i - q*(EHP*4);
        int k = r >> 2, j = r & 3;
        sWe2P[(q*EHP + k)*4 + j] = (k < EH) ? We2[k*16 + q*4 + j] : 0.f;
    }
    for (int i = tid; i < 9*EHP; i += 128) {
        int t = i / EHP, k = i - t*EHP;
        sW1f[i] = (k < EH) ? We1[(256 + t)*EH + k] : 0.f;
    }
    {
        const int g0 = blockIdx.x * NPB;
        for (int i = tid; i < NPB*EHP; i += 128)
            sA[i] = d_A[(size_t)g0*EHP + i];
    }
    for (int i = tid; i < 1024; i += 128) sWc1[i] = Wc1[i];
    if (tid < 64) sWc2[tid] = Wc2[tid];
    if (tid < 64) sbc1[tid] = bc1[tid];
    if (tid < 16) sbe2[tid] = be2[tid];

    const int g = blockIdx.x * NPB + w;
    const int boff = g & ~(NPTS - 1);
    const float cix = coors[g*3+0], ciy = coors[g*3+1], ciz = coors[g*3+2];
    const float bc2v = bc2[0];

    // precompute all 32 edges' fourier features + rel coords (one lane each)
    {
        const int j = d_idx[g*KNN_K + lane];
        sj[w*32 + lane] = j;
        const int r = boff + j;
        float rx = cix - coors[r*3+0];
        float ry = ciy - coors[r*3+1];
        float rz = ciz - coors[r*3+2];
        float d  = rx*rx + ry*ry + rz*rz;
        float* fp = sfe + (w*32 + lane)*9;
        float s, c;
        sincosf(d,        &s, &c); fp[0] = s; fp[4] = c;
        sincosf(d*0.5f,   &s, &c); fp[1] = s; fp[5] = c;
        sincosf(d*0.25f,  &s, &c); fp[2] = s; fp[6] = c;
        sincosf(d*0.125f, &s, &c); fp[3] = s; fp[7] = c;
        fp[8] = d;
        float* rp = srel + (w*32 + lane)*3;
        rp[0] = rx; rp[1] = ry; rp[2] = rz;
    }
    __syncthreads();

    const int p  = lane & 7;          // pair index this lane will own after reduce
    const int eo = (lane >> 3) & 3;   // edge-in-group this lane will own
    unsigned long long misum_pack = 0ull;
    float cax = 0.f, cay = 0.f, caz = 0.f;

    #pragma unroll 1
    for (int grp = 0; grp < 8; grp++) {
        const int e0 = grp*4;
        unsigned long long fe01[9], fe23[9];
        #pragma unroll
        for (int t = 0; t < 9; t++) {
            fe01[t] = pk2(sfe[(w*32 + e0    )*9 + t], sfe[(w*32 + e0 + 1)*9 + t]);
            fe23[t] = pk2(sfe[(w*32 + e0 + 2)*9 + t], sfe[(w*32 + e0 + 3)*9 + t]);
        }
        const float* B0 = d_Bf + (size_t)(boff + sj[w*32 + e0    ]) * EHP;
        const float* B1 = d_Bf + (size_t)(boff + sj[w*32 + e0 + 1]) * EHP;
        const float* B2 = d_Bf + (size_t)(boff + sj[w*32 + e0 + 2]) * EHP;
        const float* B3 = d_Bf + (size_t)(boff + sj[w*32 + e0 + 3]) * EHP;

        unsigned long long acc[4][8];
        #pragma unroll
        for (int e = 0; e < 4; e++)
            #pragma unroll
            for (int q = 0; q < 8; q++) acc[e][q] = 0ull;

        float b0 = B0[lane], b1 = B1[lane], b2 = B2[lane], b3 = B3[lane];

        #pragma unroll 1
        for (int it = 0; it < 17; it++) {
            const int k = it*32 + lane;
            float nb0, nb1, nb2, nb3;
            if (it < 16) {
                nb0 = B0[k + 32]; nb1 = B1[k + 32];
                nb2 = B2[k + 32]; nb3 = B3[k + 32];
            }
            const float a = sA[w*EHP + k];
            unsigned long long f01 = pk2(a + b0, a + b1);
            unsigned long long f23 = pk2(a + b2, a + b3);
            #pragma unroll
            for (int t = 0; t < 9; t++) {
                const float wv = sW1f[t*EHP + k];
                const unsigned long long wp = pk2(wv, wv);
                f01 = fma2(fe01[t], wp, f01);
                f23 = fma2(fe23[t], wp, f23);
            }
            float f0, f1, f2, f3;
            upk2(f01, f0, f1); upk2(f23, f2, f3);
            unsigned long long hp[4];
            hp[0] = pk2(siluf(f0), siluf(f0));
            hp[1] = pk2(siluf(f1), siluf(f1));
            hp[2] = pk2(siluf(f2), siluf(f2));
            hp[3] = pk2(siluf(f3), siluf(f3));
            const ulonglong2* wq = (const ulonglong2*)sWe2P;
            #pragma unroll
            for (int q = 0; q < 4; q++) {
                ulonglong2 w2 = wq[q*EHP + k];
                #pragma unroll
                for (int e = 0; e < 4; e++) {
                    acc[e][2*q]   = fma2(hp[e], w2.x, acc[e][2*q]);
                    acc[e][2*q+1] = fma2(hp[e], w2.y, acc[e][2*q+1]);
                }
            }
            b0 = nb0; b1 = nb1; b2 = nb2; b3 = nb3;
        }

        // reduce-scatter: lane L ends owning pair p=L&7 of edge (L>>3)&3
        unsigned long long r16[2][8];
        #pragma unroll
        for (int ee = 0; ee < 2; ee++)
            #pragma unroll
            for (int q = 0; q < 8; q++) {
                unsigned long long s = (lane & 16) ? acc[ee][q] : acc[ee+2][q];
                unsigned long long r = __shfl_xor_sync(0xffffffffu, s, 16);
                r16[ee][q] = add2((lane & 16) ? acc[ee+2][q] : acc[ee][q], r);
            }
        unsigned long long r8[8];
        #pragma unroll
        for (int q = 0; q < 8; q++) {
            unsigned long long s = (lane & 8) ? r16[0][q] : r16[1][q];
            unsigned long long r = __shfl_xor_sync(0xffffffffu, s, 8);
            r8[q] = add2((lane & 8) ? r16[1][q] : r16[0][q], r);
        }
        unsigned long long r4[4];
        #pragma unroll
        for (int q = 0; q < 4; q++) {
            unsigned long long s = (lane & 4) ? r8[q] : r8[q+4];
            unsigned long long r = __shfl_xor_sync(0xffffffffu, s, 4);
            r4[q] = add2((lane & 4) ? r8[q+4] : r8[q], r);
        }
        unsigned long long r2[2];
        #pragma unroll
        for (int q = 0; q < 2; q++) {
            unsigned long long s = (lane & 2) ? r4[q] : r4[q+2];
            unsigned long long r = __shfl_xor_sync(0xffffffffu, s, 2);
            r2[q] = add2((lane & 2) ? r4[q+2] : r4[q], r);
        }
        unsigned long long r1;
        {
            unsigned long long s = (lane & 1) ? r2[0] : r2[1];
            unsigned long long r = __shfl_xor_sync(0xffffffffu, s, 1);
            r1 = add2((lane & 1) ? r2[1] : r2[0], r);
        }

        float2 bp = *(const float2*)(sbe2 + 2*p);
        float lo, hi; upk2(r1, lo, hi);
        const float mlo = siluf(lo + bp.x);
        const float mhi = siluf(hi + bp.y);
        const unsigned long long mpack = pk2(mlo, mhi);
        misum_pack = add2(misum_pack, mpack);

        // rebuild full m[16] of own edge (8 u64 shfls)
        float mf[16];
        #pragma unroll
        for (int q = 0; q < 8; q++) {
            unsigned long long v = __shfl_sync(0xffffffffu, mpack, (lane & 24) | q);
            upk2(v, mf[2*q], mf[2*q+1]);
        }

        // coors MLP: lane handles 8 hidden cols [p*8, p*8+8) of its edge
        float4 hb0 = *(const float4*)(sbc1 + p*8);
        float4 hb1 = *(const float4*)(sbc1 + p*8 + 4);
        float h0 = hb0.x, h1 = hb0.y, h2 = hb0.z, h3 = hb0.w;
        float h4 = hb1.x, h5 = hb1.y, h6 = hb1.z, h7 = hb1.w;
        #pragma unroll
        for (int t = 0; t < MDIM; t++) {
            float4 wa = *(const float4*)(sWc1 + t*64 + p*8);
            float4 wb = *(const float4*)(sWc1 + t*64 + p*8 + 4);
            h0 = fmaf(mf[t], wa.x, h0); h1 = fmaf(mf[t], wa.y, h1);
            h2 = fmaf(mf[t], wa.z, h2); h3 = fmaf(mf[t], wa.w, h3);
            h4 = fmaf(mf[t], wb.x, h4); h5 = fmaf(mf[t], wb.y, h5);
            h6 = fmaf(mf[t], wb.z, h6); h7 = fmaf(mf[t], wb.w, h7);
        }
        float4 ca = *(const float4*)(sWc2 + p*8);
        float4 cb = *(const float4*)(sWc2 + p*8 + 4);
        float wv = siluf(h0)*ca.x + siluf(h1)*ca.y + siluf(h2)*ca.z + siluf(h3)*ca.w
                 + siluf(h4)*cb.x + siluf(h5)*cb.y + siluf(h6)*cb.z + siluf(h7)*cb.w;
        wv += __shfl_xor_sync(0xffffffffu, wv, 4);
        wv += __shfl_xor_sync(0xffffffffu, wv, 2);
        wv += __shfl_xor_sync(0xffffffffu, wv, 1);
        const float we = wv + bc2v;
        if (p == 0) {
            const float* rp = srel + (w*32 + e0 + eo)*3;
            cax = fmaf(we, rp[0], cax);
            cay = fmaf(we, rp[1], cay);
            caz = fmaf(we, rp[2], caz);
        }
    }

    // combine across edge groups (lanes 0,8,16,24 hold coords contributions)
    cax += __shfl_xor_sync(0xffffffffu, cax, 8);
    cax += __shfl_xor_sync(0xffffffffu, cax, 16);
    cay += __shfl_xor_sync(0xffffffffu, cay, 8);
    cay += __shfl_xor_sync(0xffffffffu, cay, 16);
    caz += __shfl_xor_sync(0xffffffffu, caz, 8);
    caz += __shfl_xor_sync(0xffffffffu, caz, 16);
    misum_pack = add2(misum_pack, __shfl_xor_sync(0xffffffffu, misum_pack, 8));
    misum_pack = add2(misum_pack, __shfl_xor_sync(0xffffffffu, misum_pack, 16));
    if (lane < 8) {
        float lo, hi; upk2(misum_pack, lo, hi);
        d_mi[(size_t)g*MDIM + 2*lane    ] = lo;
        d_mi[(size_t)g*MDIM + 2*lane + 1] = hi;
    }
    if (lane == 0) {
        out_coors[g*3+0] = cax + cix;
        out_coors[g*3+1] = cay + ciy;
        out_coors[g*3+2] = caz + ciz;
    }
}

// build concat(feats, m_i) -> d_nodein
__global__ void nodein_kernel(const float* __restrict__ feats)
{
    int i = blockIdx.x * blockDim.x + threadIdx.x;
    if (i < NG * NODE_IN) {
        int gg = i / NODE_IN, c = i - gg * NODE_IN;
        d_nodein[i] = (c < DIM) ? feats[(size_t)gg*DIM + c]
                                : d_mi[(size_t)gg*MDIM + (c - DIM)];
    }
}

// ------------------------------ launch ----------------------------------------
extern "C" void kernel_launch(void* const* d_in, const int* in_sizes, int n_in,
                              void* d_out, int out_size)
{
    const float* feats = (const float*)d_in[0];
    const float* coors = (const float*)d_in[1];
    const float* We1   = (const float*)d_in[2];
    const float* be1   = (const float*)d_in[3];
    const float* We2   = (const float*)d_in[4];
    const float* be2   = (const float*)d_in[5];
    const float* Wc1   = (const float*)d_in[6];
    const float* bc1   = (const float*)d_in[7];
    const float* Wc2   = (const float*)d_in[8];
    const float* bc2   = (const float*)d_in[9];
    const float* Wn1   = (const float*)d_in[10];
    const float* bn1   = (const float*)d_in[11];
    const float* Wn2   = (const float*)d_in[12];
    const float* bn2   = (const float*)d_in[13];

    float* out_nodes = (float*)d_out;
    float* out_coors = out_nodes + (size_t)NG * DIM;

    float *pA, *pB, *pNI, *pH;
    cudaGetSymbolAddress((void**)&pA,  d_A);
    cudaGetSymbolAddress((void**)&pB,  d_Bf);
    cudaGetSymbolAddress((void**)&pNI, d_nodein);
    cudaGetSymbolAddress((void**)&pH,  d_h);

    const int smem_floats = 4*EHP*4 + 9*EHP + NPB*EHP + 1024 + 64 + 64 + 16
                          + NPB*32*9 + NPB*32*3 + NPB*32;
    const int smem_bytes  = smem_floats * 4;   // 74432
    cudaFuncSetAttribute(edge_kernel, cudaFuncAttributeMaxDynamicSharedMemorySize, smem_bytes);

    // 1. KNN
    knn_kernel<<<NG, 256>>>(coors);

    // 2. A = feats @ We1[0:128] + be1 ; B = feats @ We1[128:256]   (ld-out = 544)
    {
        dim3 grid((EH + 63) / 64, NG / 128);
        gemm_k<<<grid, 256>>>(feats, DIM, We1,          EH, be1,     nullptr, 0, pA, EHP, NG, EH, DIM, 0);
        gemm_k<<<grid, 256>>>(feats, DIM, We1 + 128*EH, EH, nullptr, nullptr, 0, pB, EHP, NG, EH, DIM, 0);
    }

    // 3. fused edge kernel: m_i + coors_out
    edge_kernel<<<NG / NPB, 128, smem_bytes>>>(coors, We1, We2, be2, Wc1, bc1, Wc2, bc2, out_coors);

    // 4. node MLP
    nodein_kernel<<<(NG*NODE_IN + 255)/256, 256>>>(feats);
    {
        dim3 g1(NODE_H / 64, NG / 128);
        gemm_k<<<g1, 256>>>(pNI, NODE_IN, Wn1, NODE_H, bn1, nullptr, 0, pH, NODE_H, NG, NODE_H, NODE_IN, 1);
        dim3 g2(DIM / 64, NG / 128);
        gemm_k<<<g2, 256>>>(pH, NODE_H, Wn2, DIM, bn2, feats, DIM, out_nodes, DIM, NG, DIM, NODE_H, 0);
    }
}